// round 11
// baseline (speedup 1.0000x reference)
#include <cuda_runtime.h>
#include <cuda_bf16.h>
#include <stdint.h>
#include <math.h>

#define BQ 32
#define SQ 32
#define HD 128
#define CD 512
#define DD 128
#define NGRP 8             // 8 groups of 4 batches
#define NTILE (NGRP * CD)  // 4096 (group, doc) tiles
#define NCTA 296           // 2 CTAs per SM
#define INV_TEMP 50.0f

#define ATILE 32768        // A hi tile per group (4 batches x 8KB)
#define BTILE 32768        // B hi tile per doc
#define SMEM_BYTES (ATILE + 2 * BTILE)   // 96KB

__device__ float g_scores[BQ * CD];
__device__ unsigned int g_done = 0;
__device__ __align__(1024) unsigned char g_P_sw[(size_t)CD * BTILE];   // 16 MB, hi B-frag
__device__ __align__(1024) unsigned char g_Q_sw[(size_t)NGRP * ATILE]; // 256 KB, hi A-frag

// ---------------------------------------------------------------- PTX helpers
__device__ __forceinline__ uint32_t smem_u32(const void* p) {
    uint32_t a;
    asm("{ .reg .u64 t; cvta.to.shared.u64 t, %1; cvt.u32.u64 %0, t; }" : "=r"(a) : "l"(p));
    return a;
}
__device__ __forceinline__ void mbar_init(uint32_t m, uint32_t cnt) {
    asm volatile("mbarrier.init.shared.b64 [%0], %1;" :: "r"(m), "r"(cnt) : "memory");
}
__device__ __forceinline__ void mbar_expect_tx(uint32_t m, uint32_t bytes) {
    asm volatile("mbarrier.arrive.expect_tx.shared.b64 _, [%0], %1;" :: "r"(m), "r"(bytes) : "memory");
}
__device__ __forceinline__ void mbar_arrive(uint32_t m) {
    asm volatile("mbarrier.arrive.shared.b64 _, [%0];" :: "r"(m) : "memory");
}
__device__ __forceinline__ void mbar_wait(uint32_t m, uint32_t parity) {
    uint32_t done;
    asm volatile("{\n\t.reg .pred p;\n\t"
        "mbarrier.try_wait.parity.acquire.cta.shared::cta.b64 p, [%1], %2;\n\t"
        "selp.b32 %0, 1, 0, p;\n\t}"
        : "=r"(done) : "r"(m), "r"(parity) : "memory");
    while (!done) {
        asm volatile("{\n\t.reg .pred p;\n\t"
            "mbarrier.try_wait.parity.acquire.cta.shared::cta.b64 p, [%1], %2, 0x989680;\n\t"
            "selp.b32 %0, 1, 0, p;\n\t}"
            : "=r"(done) : "r"(m), "r"(parity) : "memory");
    }
}
__device__ __forceinline__ void bulk_copy_g2s(uint32_t dst, const void* src, uint32_t bytes, uint32_t mbar) {
    asm volatile("cp.async.bulk.shared::cluster.global.mbarrier::complete_tx::bytes [%0], [%1], %2, [%3];"
        :: "r"(dst), "l"(src), "r"(bytes), "r"(mbar) : "memory");
}
__device__ __forceinline__ void mma_bf16(float* c, const uint32_t* a, const uint32_t* b) {
    asm volatile("mma.sync.aligned.m16n8k16.row.col.f32.bf16.bf16.f32 "
        "{%0,%1,%2,%3}, {%4,%5,%6,%7}, {%8,%9}, {%0,%1,%2,%3};"
        : "+f"(c[0]), "+f"(c[1]), "+f"(c[2]), "+f"(c[3])
        : "r"(a[0]), "r"(a[1]), "r"(a[2]), "r"(a[3]), "r"(b[0]), "r"(b[1]));
}
__device__ __forceinline__ uint32_t bf16x2_hi(float f0, float f1) {
    __nv_bfloat16 h0 = __float2bfloat16(f0);
    __nv_bfloat16 h1 = __float2bfloat16(f1);
    unsigned short u0 = *reinterpret_cast<unsigned short*>(&h0);
    unsigned short u1 = *reinterpret_cast<unsigned short*>(&h1);
    return (uint32_t)u0 | ((uint32_t)u1 << 16);
}

// ---------------------------------------------------------------------------
// convert: P -> per-doc 32KB hi B-frag; Q -> per-group 32KB hi A-frag.
// B: uint2 {hi_ri0, hi_ri1} at c*BTILE + ((k*16+n)*32+lane)*8
//    (h = k*16 + ri*8 + tg*2 {,+1}, d = n*8 + gr)
// A: uint4 {ri0..ri3} at g*ATILE + batch*8192 + ((m*8+k)*32+lane)*16
//    (s = m*16 + gr + (ri&1)*8, h = k*16 + tg*2 + (ri>>1)*8 {,+1})
// ---------------------------------------------------------------------------
__global__ void convert_kernel(const float* __restrict__ P, const float* __restrict__ Q) {
    int idx = blockIdx.x * blockDim.x + threadIdx.x;
    if (idx < CD * 4096) {
        int lane = idx & 31;
        int n    = (idx >> 5) & 15;
        int k    = (idx >> 9) & 7;
        int c    = idx >> 12;
        int tg = lane & 3, gr = lane >> 2;
        int d = n * 8 + gr;
        const float* s = P + ((size_t)c * DD + d) * HD;
        int h0 = k * 16 + tg * 2;
        float2 f0 = *reinterpret_cast<const float2*>(s + h0);
        float2 f1 = *reinterpret_cast<const float2*>(s + h0 + 8);
        uint2 v;
        v.x = bf16x2_hi(f0.x, f0.y);
        v.y = bf16x2_hi(f1.x, f1.y);
        *reinterpret_cast<uint2*>(g_P_sw + (size_t)c * BTILE
            + (size_t)(((k * 16 + n) * 32 + lane) * 8)) = v;
    } else {
        int qi = idx - CD * 4096;
        if (qi >= NGRP * 2048) return;
        int lane  = qi & 31;
        int k     = (qi >> 5) & 7;
        int m     = (qi >> 8) & 1;
        int batch = (qi >> 9) & 3;
        int g     = qi >> 11;
        int tg = lane & 3, gr = lane >> 2;
        int b = g * 4 + batch;
        uint32_t w[4];
#pragma unroll
        for (int ri = 0; ri < 4; ++ri) {
            int srow = m * 16 + gr + (ri & 1) * 8;
            int h    = k * 16 + tg * 2 + (ri >> 1) * 8;
            const float* s = Q + ((size_t)b * SQ + srow) * HD + h;
            w[ri] = bf16x2_hi(s[0], s[1]);
        }
        uint4 v = {w[0], w[1], w[2], w[3]};
        *reinterpret_cast<uint4*>(g_Q_sw + (size_t)g * ATILE + (size_t)batch * 8192
            + (size_t)(((m * 8 + k) * 32 + lane) * 16)) = v;
    }
}

// ---------------------------------------------------------------------------
// maxsim: 296 persistent CTAs (2/SM), 256 threads. Tile t -> (g=t>>9, c=t&511).
// Warp w: batch=w>>1, dhalf=w&1. 1-pass bf16-hi MMA -> top-2 d per (s) ->
// exact fp32 refine of both candidates via LDG on raw Q/P -> max/sum.
// Last CTA (atomic ticket) computes the final loss.
// ---------------------------------------------------------------------------
__global__ __launch_bounds__(256, 2)
void maxsim_kernel(const float* __restrict__ Qraw, const float* __restrict__ Praw,
                   float* __restrict__ out) {
    extern __shared__ __align__(128) unsigned char dyn[];
    __shared__ __align__(8) unsigned long long bars[5];  // QFULL, BFULL[2], BFREE[2]
    __shared__ float sel[4][32][2][2];   // [batch][s][dhalf][top1,top2]
    __shared__ float smax2[4][32];
    __shared__ float part[32];
    __shared__ unsigned int isLast;

    const int tid = threadIdx.x, w = tid >> 5, lane = tid & 31;
    const int batch = w >> 1, dhalf = w & 1;
    const int tg = lane & 3, gr = lane >> 2;

    const int start = (blockIdx.x * NTILE) / NCTA;
    const int end   = ((blockIdx.x + 1) * NTILE) / NCTA;
    const int L     = end - start;

    const uint32_t QFULL  = smem_u32(&bars[0]);
    const uint32_t BFULL0 = smem_u32(&bars[1]);
    const uint32_t BFREE0 = smem_u32(&bars[3]);
    const uint32_t A_S    = smem_u32(dyn);
    const uint32_t B_S    = smem_u32(dyn + ATILE);

    if (tid == 0) {
        mbar_init(QFULL, 1);
        mbar_init(BFULL0, 1);     mbar_init(BFULL0 + 8, 1);
        mbar_init(BFREE0, 8);     mbar_init(BFREE0 + 8, 8);
    }
    __syncthreads();

    if (tid == 0) {
        mbar_expect_tx(BFULL0, BTILE);
        bulk_copy_g2s(B_S, g_P_sw + (size_t)(start & 511) * BTILE, BTILE, BFULL0);
        if (L > 1) {
            mbar_expect_tx(BFULL0 + 8, BTILE);
            bulk_copy_g2s(B_S + BTILE, g_P_sw + (size_t)((start + 1) & 511) * BTILE, BTILE, BFULL0 + 8);
        }
    }

    int cur_g = -1, aloads = 0;

    for (int j = 0; j < L; ++j) {
        const int t = start + j;
        const int g = t >> 9;
        const int c = t & 511;
        const int st = j & 1;
        const int ph = (j >> 1) & 1;

        if (g != cur_g) {
            __syncthreads();
            if (tid == 0) {
                mbar_expect_tx(QFULL, ATILE);
                bulk_copy_g2s(A_S, g_Q_sw + (size_t)g * ATILE, ATILE, QFULL);
            }
            mbar_wait(QFULL, aloads & 1);
            ++aloads;
            cur_g = g;
        }

        mbar_wait(BFULL0 + 8 * st, ph);

        const unsigned char* aBase = dyn + batch * 8192;          // hi A-frag
        const unsigned char* stg   = dyn + ATILE + st * BTILE;    // hi B-frag

        float acc[2][8][4];
#pragma unroll
        for (int mm = 0; mm < 2; ++mm)
#pragma unroll
            for (int nn = 0; nn < 8; ++nn)
#pragma unroll
                for (int q = 0; q < 4; ++q) acc[mm][nn][q] = 0.0f;

#pragma unroll
        for (int k = 0; k < 8; ++k) {
            uint4 A0 = *reinterpret_cast<const uint4*>(aBase + ((0 * 8 + k) * 32 + lane) * 16);
            uint4 A1 = *reinterpret_cast<const uint4*>(aBase + ((1 * 8 + k) * 32 + lane) * 16);
#pragma unroll
            for (int n = 0; n < 8; ++n) {
                uint2 B = *reinterpret_cast<const uint2*>(
                    stg + ((k * 16 + dhalf * 8 + n) * 32 + lane) * 8);
                mma_bf16(acc[0][n], &A0.x, &B.x);
                mma_bf16(acc[1][n], &A1.x, &B.x);
            }
        }

        if (lane == 0) mbar_arrive(BFREE0 + 8 * st);  // stage consumed

        if (tid == 0 && j + 2 < L) {
            mbar_wait(BFREE0 + 8 * st, ph);
            mbar_expect_tx(BFULL0 + 8 * st, BTILE);
            bulk_copy_g2s(B_S + st * BTILE,
                          g_P_sw + (size_t)((start + j + 2) & 511) * BTILE, BTILE,
                          BFULL0 + 8 * st);
        }

        // ---- top-2 selection over d (packed idx in low 7 mantissa bits) ----
        float t1[2][2], t2[2][2];
#pragma unroll
        for (int mm = 0; mm < 2; ++mm)
#pragma unroll
            for (int rb = 0; rb < 2; ++rb) { t1[mm][rb] = -3.402823e38f; t2[mm][rb] = -3.402823e38f; }
#pragma unroll
        for (int mm = 0; mm < 2; ++mm)
#pragma unroll
            for (int n = 0; n < 8; ++n)
#pragma unroll
                for (int q = 0; q < 4; ++q) {
                    int rb = q >> 1, e = q & 1;
                    uint32_t d = (uint32_t)(dhalf * 64 + n * 8 + tg * 2 + e);
                    float pv = __uint_as_float(
                        (__float_as_uint(acc[mm][n][q]) & 0xFFFFFF80u) | d);
                    if (pv > t1[mm][rb]) { t2[mm][rb] = t1[mm][rb]; t1[mm][rb] = pv; }
                    else t2[mm][rb] = fmaxf(t2[mm][rb], pv);
                }
#pragma unroll
        for (int off = 1; off <= 2; off <<= 1) {
#pragma unroll
            for (int mm = 0; mm < 2; ++mm)
#pragma unroll
                for (int rb = 0; rb < 2; ++rb) {
                    float o1 = __shfl_xor_sync(0xffffffffu, t1[mm][rb], off);
                    float o2 = __shfl_xor_sync(0xffffffffu, t2[mm][rb], off);
                    float hi = fmaxf(t1[mm][rb], o1);
                    float ws = (t1[mm][rb] >= o1) ? t2[mm][rb] : o2;
                    float lo = fmaxf(fminf(t1[mm][rb], o1), ws);
                    t1[mm][rb] = hi; t2[mm][rb] = lo;
                }
        }
        if (tg == 0) {
#pragma unroll
            for (int mm = 0; mm < 2; ++mm)
#pragma unroll
                for (int rb = 0; rb < 2; ++rb) {
                    int s = mm * 16 + rb * 8 + gr;
                    sel[batch][s][dhalf][0] = t1[mm][rb];
                    sel[batch][s][dhalf][1] = t2[mm][rb];
                }
        }
        asm volatile("bar.sync %0, %1;" :: "r"(1 + batch), "r"(64) : "memory");

        // ---- exact fp32 refine of both top-2 candidates ----
        {
            int tb   = dhalf * 32 + lane;   // 0..63 within batch pair
            int s    = tb >> 1;
            int rank = tb & 1;
            float a1 = sel[batch][s][0][0], a2 = sel[batch][s][0][1];
            float b1 = sel[batch][s][1][0], b2 = sel[batch][s][1][1];
            float m1 = fmaxf(a1, b1);
            float ws = (a1 >= b1) ? a2 : b2;
            float m2 = fmaxf(fminf(a1, b1), ws);
            float pick = rank ? m2 : m1;
            int d = (int)(__float_as_uint(pick) & 0x7Fu);

            const float4* qr = reinterpret_cast<const float4*>(
                Qraw + ((size_t)(g * 4 + batch) * SQ + s) * HD);
            const float4* pr = reinterpret_cast<const float4*>(
                Praw + ((size_t)c * DD + d) * HD);
            float s0 = 0.f, s1 = 0.f, s2 = 0.f, s3 = 0.f;
#pragma unroll
            for (int i = 0; i < 32; i += 4) {
                float4 q0 = qr[i], q1 = qr[i + 1], q2 = qr[i + 2], q3 = qr[i + 3];
                float4 p0 = pr[i], p1 = pr[i + 1], p2 = pr[i + 2], p3 = pr[i + 3];
                s0 = fmaf(q0.x, p0.x, fmaf(q0.y, p0.y, fmaf(q0.z, p0.z, fmaf(q0.w, p0.w, s0))));
                s1 = fmaf(q1.x, p1.x, fmaf(q1.y, p1.y, fmaf(q1.z, p1.z, fmaf(q1.w, p1.w, s1))));
                s2 = fmaf(q2.x, p2.x, fmaf(q2.y, p2.y, fmaf(q2.z, p2.z, fmaf(q2.w, p2.w, s2))));
                s3 = fmaf(q3.x, p3.x, fmaf(q3.y, p3.y, fmaf(q3.z, p3.z, fmaf(q3.w, p3.w, s3))));
            }
            float dot = (s0 + s1) + (s2 + s3);
            float other = __shfl_xor_sync(0xffffffffu, dot, 1);
            float mxv = fmaxf(dot, other);
            if (rank == 0) smax2[batch][s] = mxv;
        }
        asm volatile("bar.sync %0, %1;" :: "r"(1 + batch), "r"(64) : "memory");
        if (dhalf == 0) {
            float v = smax2[batch][lane];
#pragma unroll
            for (int off = 16; off; off >>= 1) v += __shfl_xor_sync(0xffffffffu, v, off);
            if (lane == 0) g_scores[(g * 4 + batch) * CD + c] = v * INV_TEMP;
        }
    }

    // ---- last CTA computes loss ----
    __syncthreads();
    if (tid == 0) {
        __threadfence();
        unsigned int o = atomicAdd(&g_done, 1u);
        isLast = (o == NCTA - 1) ? 1u : 0u;
    }
    __syncthreads();
    if (isLast) {
        __threadfence();
#pragma unroll
        for (int r = 0; r < 4; ++r) {
            int row = w * 4 + r;
            const float* rp = g_scores + row * CD;
            float4 v4[4];
#pragma unroll
            for (int k = 0; k < 4; ++k)
                v4[k] = *reinterpret_cast<const float4*>(rp + (lane + k * 32) * 4);
            float mx = -3.402823e38f;
#pragma unroll
            for (int k = 0; k < 4; ++k)
                mx = fmaxf(mx, fmaxf(fmaxf(v4[k].x, v4[k].y), fmaxf(v4[k].z, v4[k].w)));
#pragma unroll
            for (int off = 16; off; off >>= 1) mx = fmaxf(mx, __shfl_xor_sync(0xffffffffu, mx, off));
            float se = 0.0f;
#pragma unroll
            for (int k = 0; k < 4; ++k)
                se += expf(v4[k].x - mx) + expf(v4[k].y - mx) + expf(v4[k].z - mx) + expf(v4[k].w - mx);
#pragma unroll
            for (int off = 16; off; off >>= 1) se += __shfl_xor_sync(0xffffffffu, se, off);
            if (lane == 0) part[row] = mx + logf(se) - rp[0];
        }
        __syncthreads();
        if (w == 0) {
            float v = part[lane];
#pragma unroll
            for (int off = 16; off; off >>= 1) v += __shfl_xor_sync(0xffffffffu, v, off);
            if (lane == 0) out[0] = v * (1.0f / (float)BQ);
        }
        if (tid == 0) g_done = 0;   // reset for next graph replay
    }
}

extern "C" void kernel_launch(void* const* d_in, const int* in_sizes, int n_in,
                              void* d_out, int out_size) {
    const float* Q = (const float*)d_in[0];
    const float* P = (const float*)d_in[1];
    if (n_in >= 2 && in_sizes[0] != BQ * SQ * HD) {
        const float* t = Q; Q = P; P = t;
    }
    float* out = (float*)d_out;

    static bool attr_set = false;
    if (!attr_set) {
        cudaFuncSetAttribute(maxsim_kernel, cudaFuncAttributeMaxDynamicSharedMemorySize, SMEM_BYTES);
        attr_set = true;
    }

    const int conv_total = CD * 4096 + NGRP * 2048;
    convert_kernel<<<(conv_total + 255) / 256, 256>>>(P, Q);
    maxsim_kernel<<<NCTA, 256, SMEM_BYTES>>>(Q, P, out);
}

// round 12
// speedup vs baseline: 2.5618x; 2.5618x over previous
#include <cuda_runtime.h>
#include <cuda_fp16.h>
#include <stdint.h>
#include <math.h>

#define BQ 32
#define SQ 32
#define HD 128
#define CD 512
#define DD 128
#define NGRP 8             // 8 groups of 4 batches (M=128 rows of A)
#define NTILE (NGRP * CD)  // 4096 (group, doc) tiles
#define NCTA 148
#define INV_TEMP 50.0f

#define ATILE 65536        // A tile per group: 4 batches x (hi 8KB | lo 8KB)
#define BTILE 32768        // B tile per doc: hi fp16 only
#define SMEM_BYTES (ATILE + 2 * BTILE)   // 128KB

__device__ float g_scores[BQ * CD];
__device__ unsigned int g_done = 0;
__device__ __align__(1024) unsigned char g_P_sw[(size_t)CD * BTILE];   // 16 MB, fp16-hi B-frag
__device__ __align__(1024) unsigned char g_Q_sw[(size_t)NGRP * ATILE]; // 512 KB, fp16 hi/lo A-frag

// ---------------------------------------------------------------- PTX helpers
__device__ __forceinline__ uint32_t smem_u32(const void* p) {
    uint32_t a;
    asm("{ .reg .u64 t; cvta.to.shared.u64 t, %1; cvt.u32.u64 %0, t; }" : "=r"(a) : "l"(p));
    return a;
}
__device__ __forceinline__ void mbar_init(uint32_t m, uint32_t cnt) {
    asm volatile("mbarrier.init.shared.b64 [%0], %1;" :: "r"(m), "r"(cnt) : "memory");
}
__device__ __forceinline__ void mbar_expect_tx(uint32_t m, uint32_t bytes) {
    asm volatile("mbarrier.arrive.expect_tx.shared.b64 _, [%0], %1;" :: "r"(m), "r"(bytes) : "memory");
}
__device__ __forceinline__ void mbar_arrive(uint32_t m) {
    asm volatile("mbarrier.arrive.shared.b64 _, [%0];" :: "r"(m) : "memory");
}
__device__ __forceinline__ void mbar_wait(uint32_t m, uint32_t parity) {
    uint32_t done;
    asm volatile("{\n\t.reg .pred p;\n\t"
        "mbarrier.try_wait.parity.acquire.cta.shared::cta.b64 p, [%1], %2;\n\t"
        "selp.b32 %0, 1, 0, p;\n\t}"
        : "=r"(done) : "r"(m), "r"(parity) : "memory");
    while (!done) {
        asm volatile("{\n\t.reg .pred p;\n\t"
            "mbarrier.try_wait.parity.acquire.cta.shared::cta.b64 p, [%1], %2, 0x989680;\n\t"
            "selp.b32 %0, 1, 0, p;\n\t}"
            : "=r"(done) : "r"(m), "r"(parity) : "memory");
    }
}
__device__ __forceinline__ void bulk_copy_g2s(uint32_t dst, const void* src, uint32_t bytes, uint32_t mbar) {
    asm volatile("cp.async.bulk.shared::cluster.global.mbarrier::complete_tx::bytes [%0], [%1], %2, [%3];"
        :: "r"(dst), "l"(src), "r"(bytes), "r"(mbar) : "memory");
}
// warp mma: D(f32 16x8) += A(f16 16x16, row) * B(f16 16x8, col)
__device__ __forceinline__ void mma_f16(float* c, const uint32_t* a, const uint32_t* b) {
    asm volatile("mma.sync.aligned.m16n8k16.row.col.f32.f16.f16.f32 "
        "{%0,%1,%2,%3}, {%4,%5,%6,%7}, {%8,%9}, {%0,%1,%2,%3};"
        : "+f"(c[0]), "+f"(c[1]), "+f"(c[2]), "+f"(c[3])
        : "r"(a[0]), "r"(a[1]), "r"(a[2]), "r"(a[3]), "r"(b[0]), "r"(b[1]));
}
__device__ __forceinline__ uint32_t f16x2_pack(__half a, __half b) {
    __half2 h = __halves2half2(a, b);
    return *reinterpret_cast<uint32_t*>(&h);
}
__device__ __forceinline__ uint32_t f16x2_hi(float f0, float f1, uint32_t& lo_out) {
    __half h0 = __float2half_rn(f0);
    __half h1 = __float2half_rn(f1);
    __half l0 = __float2half_rn(f0 - __half2float(h0));
    __half l1 = __float2half_rn(f1 - __half2float(h1));
    lo_out = f16x2_pack(l0, l1);
    return f16x2_pack(h0, h1);
}

// ---------------------------------------------------------------------------
// convert: P -> per-doc 32KB fp16-hi B-frag; Q -> per-group 64KB fp16 hi/lo A-frag.
// B: uint2 {hi_ri0, hi_ri1} at c*BTILE + ((k*16+n)*32+lane)*8
//    (h = k*16 + ri*8 + tg*2 {,+1}, d = n*8 + gr)
// A: per batch 16KB { hi 8KB | lo 8KB }; word at ((m*8+k)*32+lane)*16 + ri*4
//    (s = m*16 + gr + (ri&1)*8, h = k*16 + tg*2 + (ri>>1)*8 {,+1})
// ---------------------------------------------------------------------------
__global__ void convert_kernel(const float* __restrict__ P, const float* __restrict__ Q) {
    int idx = blockIdx.x * blockDim.x + threadIdx.x;
    if (idx < CD * 4096) {
        int lane = idx & 31;
        int n    = (idx >> 5) & 15;
        int k    = (idx >> 9) & 7;
        int c    = idx >> 12;
        int tg = lane & 3, gr = lane >> 2;
        int d = n * 8 + gr;
        const float* s = P + ((size_t)c * DD + d) * HD;
        int h0 = k * 16 + tg * 2;
        float2 f0 = *reinterpret_cast<const float2*>(s + h0);
        float2 f1 = *reinterpret_cast<const float2*>(s + h0 + 8);
        uint2 v;
        v.x = f16x2_pack(__float2half_rn(f0.x), __float2half_rn(f0.y));
        v.y = f16x2_pack(__float2half_rn(f1.x), __float2half_rn(f1.y));
        *reinterpret_cast<uint2*>(g_P_sw + (size_t)c * BTILE
            + (size_t)(((k * 16 + n) * 32 + lane) * 8)) = v;
    } else {
        int qi = idx - CD * 4096;
        if (qi >= NGRP * 8192) return;
        int ri    = qi & 3;
        int lane  = (qi >> 2) & 31;
        int k     = (qi >> 7) & 7;
        int m     = (qi >> 10) & 1;
        int batch = (qi >> 11) & 3;
        int g     = qi >> 13;
        int tg = lane & 3, gr = lane >> 2;
        int srow = m * 16 + gr + (ri & 1) * 8;
        int h    = k * 16 + tg * 2 + (ri >> 1) * 8;
        int b    = g * 4 + batch;

        const float* s = Q + ((size_t)b * SQ + srow) * HD + h;
        uint32_t lo, hi = f16x2_hi(s[0], s[1], lo);

        size_t off = (size_t)g * ATILE + (size_t)batch * 16384
                   + (size_t)(((m * 8 + k) * 32 + lane) * 16 + ri * 4);
        *reinterpret_cast<uint32_t*>(g_Q_sw + off)        = hi;
        *reinterpret_cast<uint32_t*>(g_Q_sw + off + 8192) = lo;
    }
}

// ---------------------------------------------------------------------------
// maxsim: 148 persistent CTAs, 256 threads. Tile t -> (g=t>>9, c=t&511).
// Warp w: batch=w>>1, dhalf=w&1. 2-pass fp16 split: acc += Ah*Bh + Al*Bh.
// Last CTA (atomic ticket) computes the final loss.
// ---------------------------------------------------------------------------
__global__ __launch_bounds__(256, 1)
void maxsim_kernel(float* __restrict__ out) {
    extern __shared__ __align__(128) unsigned char dyn[];
    __shared__ __align__(8) unsigned long long bars[5];  // QFULL, BFULL[2], BFREE[2]
    __shared__ float smax[2][4][2][32];
    __shared__ float part[32];
    __shared__ unsigned int isLast;

    const int tid = threadIdx.x, w = tid >> 5, lane = tid & 31;
    const int batch = w >> 1, dhalf = w & 1;
    const int tg = lane & 3, gr = lane >> 2;

    const int start = (blockIdx.x * NTILE) / NCTA;
    const int end   = ((blockIdx.x + 1) * NTILE) / NCTA;
    const int L     = end - start;

    const uint32_t QFULL  = smem_u32(&bars[0]);
    const uint32_t BFULL0 = smem_u32(&bars[1]);
    const uint32_t BFREE0 = smem_u32(&bars[3]);
    const uint32_t A_S    = smem_u32(dyn);
    const uint32_t B_S    = smem_u32(dyn + ATILE);

    if (tid == 0) {
        mbar_init(QFULL, 1);
        mbar_init(BFULL0, 1);     mbar_init(BFULL0 + 8, 1);
        mbar_init(BFREE0, 8);     mbar_init(BFREE0 + 8, 8);
    }
    __syncthreads();

    // prefetch B for j = 0, 1
    if (tid == 0) {
        mbar_expect_tx(BFULL0, BTILE);
        bulk_copy_g2s(B_S, g_P_sw + (size_t)(start & 511) * BTILE, BTILE, BFULL0);
        if (L > 1) {
            mbar_expect_tx(BFULL0 + 8, BTILE);
            bulk_copy_g2s(B_S + BTILE, g_P_sw + (size_t)((start + 1) & 511) * BTILE, BTILE, BFULL0 + 8);
        }
    }

    int cur_g = -1, aloads = 0;

    for (int j = 0; j < L; ++j) {
        const int t = start + j;
        const int g = t >> 9;
        const int c = t & 511;
        const int st = j & 1;
        const int ph = (j >> 1) & 1;

        if (g != cur_g) {
            __syncthreads();  // all warps done with old A
            if (tid == 0) {
                mbar_expect_tx(QFULL, ATILE);
                bulk_copy_g2s(A_S, g_Q_sw + (size_t)g * ATILE, ATILE, QFULL);
            }
            mbar_wait(QFULL, aloads & 1);
            ++aloads;
            cur_g = g;
        }

        mbar_wait(BFULL0 + 8 * st, ph);

        const unsigned char* aBase = dyn + batch * 16384;          // hi; lo at +8192
        const unsigned char* stg   = dyn + ATILE + st * BTILE;     // fp16-hi B-frag

        float acc[2][8][4];
#pragma unroll
        for (int mm = 0; mm < 2; ++mm)
#pragma unroll
            for (int nn = 0; nn < 8; ++nn)
#pragma unroll
                for (int q = 0; q < 4; ++q) acc[mm][nn][q] = 0.0f;

#pragma unroll
        for (int k = 0; k < 8; ++k) {
            uint4 Ah0 = *reinterpret_cast<const uint4*>(aBase + ((0 * 8 + k) * 32 + lane) * 16);
            uint4 Ah1 = *reinterpret_cast<const uint4*>(aBase + ((1 * 8 + k) * 32 + lane) * 16);
            uint4 Al0 = *reinterpret_cast<const uint4*>(aBase + 8192 + ((0 * 8 + k) * 32 + lane) * 16);
            uint4 Al1 = *reinterpret_cast<const uint4*>(aBase + 8192 + ((1 * 8 + k) * 32 + lane) * 16);
#pragma unroll
            for (int n = 0; n < 8; ++n) {
                uint2 B = *reinterpret_cast<const uint2*>(
                    stg + ((k * 16 + dhalf * 8 + n) * 32 + lane) * 8);
                mma_f16(acc[0][n], &Ah0.x, &B.x);   // Ah*Bh
                mma_f16(acc[1][n], &Ah1.x, &B.x);
                mma_f16(acc[0][n], &Al0.x, &B.x);   // Al*Bh
                mma_f16(acc[1][n], &Al1.x, &B.x);
            }
        }

        if (lane == 0) mbar_arrive(BFREE0 + 8 * st);  // this stage consumed

        // producer: refill this stage with doc of tile j+2
        if (tid == 0 && j + 2 < L) {
            mbar_wait(BFREE0 + 8 * st, ph);
            mbar_expect_tx(BFULL0 + 8 * st, BTILE);
            bulk_copy_g2s(B_S + st * BTILE,
                          g_P_sw + (size_t)((start + j + 2) & 511) * BTILE, BTILE,
                          BFULL0 + 8 * st);
        }

        // ---- epilogue: max over d, then cross-warp max + sum over s ----
        float m00 = -3.402823e38f, m01 = m00, m10 = m00, m11 = m00;
#pragma unroll
        for (int n = 0; n < 8; ++n) {
            m00 = fmaxf(m00, fmaxf(acc[0][n][0], acc[0][n][1]));
            m01 = fmaxf(m01, fmaxf(acc[0][n][2], acc[0][n][3]));
            m10 = fmaxf(m10, fmaxf(acc[1][n][0], acc[1][n][1]));
            m11 = fmaxf(m11, fmaxf(acc[1][n][2], acc[1][n][3]));
        }
#pragma unroll
        for (int off = 1; off <= 2; off <<= 1) {
            m00 = fmaxf(m00, __shfl_xor_sync(0xffffffffu, m00, off));
            m01 = fmaxf(m01, __shfl_xor_sync(0xffffffffu, m01, off));
            m10 = fmaxf(m10, __shfl_xor_sync(0xffffffffu, m10, off));
            m11 = fmaxf(m11, __shfl_xor_sync(0xffffffffu, m11, off));
        }
        const int buf = j & 1;
        if (tg == 0) {
            smax[buf][batch][dhalf][gr]      = m00;  // s = gr
            smax[buf][batch][dhalf][gr + 8]  = m01;  // s = gr+8
            smax[buf][batch][dhalf][gr + 16] = m10;  // s = 16+gr
            smax[buf][batch][dhalf][gr + 24] = m11;  // s = 24+gr
        }
        asm volatile("bar.sync %0, %1;" :: "r"(1 + batch), "r"(64) : "memory");
        if (dhalf == 0) {
            float v = fmaxf(smax[buf][batch][0][lane], smax[buf][batch][1][lane]);
#pragma unroll
            for (int off = 16; off; off >>= 1) v += __shfl_xor_sync(0xffffffffu, v, off);
            if (lane == 0) g_scores[(g * 4 + batch) * CD + c] = v * INV_TEMP;
        }
    }

    // ---- last CTA computes loss ----
    __syncthreads();
    if (tid == 0) {
        __threadfence();
        unsigned int o = atomicAdd(&g_done, 1u);
        isLast = (o == NCTA - 1) ? 1u : 0u;
    }
    __syncthreads();
    if (isLast) {
        __threadfence();
#pragma unroll
        for (int r = 0; r < 4; ++r) {
            int row = w * 4 + r;
            const float* rp = g_scores + row * CD;
            float4 v4[4];
#pragma unroll
            for (int k = 0; k < 4; ++k)
                v4[k] = *reinterpret_cast<const float4*>(rp + (lane + k * 32) * 4);
            float mx = -3.402823e38f;
#pragma unroll
            for (int k = 0; k < 4; ++k)
                mx = fmaxf(mx, fmaxf(fmaxf(v4[k].x, v4[k].y), fmaxf(v4[k].z, v4[k].w)));
#pragma unroll
            for (int off = 16; off; off >>= 1) mx = fmaxf(mx, __shfl_xor_sync(0xffffffffu, mx, off));
            float se = 0.0f;
#pragma unroll
            for (int k = 0; k < 4; ++k)
                se += expf(v4[k].x - mx) + expf(v4[k].y - mx) + expf(v4[k].z - mx) + expf(v4[k].w - mx);
#pragma unroll
            for (int off = 16; off; off >>= 1) se += __shfl_xor_sync(0xffffffffu, se, off);
            if (lane == 0) part[row] = mx + logf(se) - rp[0];
        }
        __syncthreads();
        if (w == 0) {
            float v = part[lane];
#pragma unroll
            for (int off = 16; off; off >>= 1) v += __shfl_xor_sync(0xffffffffu, v, off);
            if (lane == 0) out[0] = v * (1.0f / (float)BQ);
        }
        if (tid == 0) g_done = 0;   // reset for next graph replay
    }
}

extern "C" void kernel_launch(void* const* d_in, const int* in_sizes, int n_in,
                              void* d_out, int out_size) {
    const float* Q = (const float*)d_in[0];
    const float* P = (const float*)d_in[1];
    if (n_in >= 2 && in_sizes[0] != BQ * SQ * HD) {
        const float* t = Q; Q = P; P = t;
    }
    float* out = (float*)d_out;

    static bool attr_set = false;
    if (!attr_set) {
        cudaFuncSetAttribute(maxsim_kernel, cudaFuncAttributeMaxDynamicSharedMemorySize, SMEM_BYTES);
        attr_set = true;
    }

    const int conv_total = CD * 4096 + NGRP * 8192;
    convert_kernel<<<(conv_total + 255) / 256, 256>>>(P, Q);
    maxsim_kernel<<<NCTA, 256, SMEM_BYTES>>>(out);
}

// round 14
// speedup vs baseline: 2.5970x; 1.0137x over previous
#include <cuda_runtime.h>
#include <cuda_fp16.h>
#include <stdint.h>
#include <math.h>

#define BQ 32
#define SQ 32
#define HD 128
#define CD 512
#define DD 128
#define NGRP 16            // 16 groups of 2 batches (M=64 rows of A)
#define NTILE (NGRP * CD)  // 8192 (group, doc) tiles
#define NCTA 296           // 2 CTAs per SM
#define INV_TEMP 50.0f

#define ATILE 32768        // A tile per group: 2 batches x (hi 8KB | lo 8KB)
#define BTILE 32768        // B tile per doc: hi fp16 only
#define SMEM_BYTES (ATILE + 2 * BTILE)   // 96KB -> 2 CTAs/SM

__device__ float g_scores[BQ * CD];
__device__ unsigned int g_done = 0;
__device__ __align__(1024) unsigned char g_P_sw[(size_t)CD * BTILE];   // 16 MB, fp16-hi B-frag
__device__ __align__(1024) unsigned char g_Q_sw[(size_t)NGRP * ATILE]; // 512 KB, fp16 hi/lo A-frag

// ---------------------------------------------------------------- PTX helpers
__device__ __forceinline__ uint32_t smem_u32(const void* p) {
    uint32_t a;
    asm("{ .reg .u64 t; cvta.to.shared.u64 t, %1; cvt.u32.u64 %0, t; }" : "=r"(a) : "l"(p));
    return a;
}
__device__ __forceinline__ void mbar_init(uint32_t m, uint32_t cnt) {
    asm volatile("mbarrier.init.shared.b64 [%0], %1;" :: "r"(m), "r"(cnt) : "memory");
}
__device__ __forceinline__ void mbar_expect_tx(uint32_t m, uint32_t bytes) {
    asm volatile("mbarrier.arrive.expect_tx.shared.b64 _, [%0], %1;" :: "r"(m), "r"(bytes) : "memory");
}
__device__ __forceinline__ void mbar_arrive(uint32_t m) {
    asm volatile("mbarrier.arrive.shared.b64 _, [%0];" :: "r"(m) : "memory");
}
__device__ __forceinline__ void mbar_wait(uint32_t m, uint32_t parity) {
    uint32_t done;
    asm volatile("{\n\t.reg .pred p;\n\t"
        "mbarrier.try_wait.parity.acquire.cta.shared::cta.b64 p, [%1], %2;\n\t"
        "selp.b32 %0, 1, 0, p;\n\t}"
        : "=r"(done) : "r"(m), "r"(parity) : "memory");
    while (!done) {
        asm volatile("{\n\t.reg .pred p;\n\t"
            "mbarrier.try_wait.parity.acquire.cta.shared::cta.b64 p, [%1], %2, 0x989680;\n\t"
            "selp.b32 %0, 1, 0, p;\n\t}"
            : "=r"(done) : "r"(m), "r"(parity) : "memory");
    }
}
__device__ __forceinline__ void bulk_copy_g2s(uint32_t dst, const void* src, uint32_t bytes, uint32_t mbar) {
    asm volatile("cp.async.bulk.shared::cluster.global.mbarrier::complete_tx::bytes [%0], [%1], %2, [%3];"
        :: "r"(dst), "l"(src), "r"(bytes), "r"(mbar) : "memory");
}
// warp mma: D(f32 16x8) += A(f16 16x16, row) * B(f16 16x8, col)
__device__ __forceinline__ void mma_f16(float* c, const uint32_t* a, const uint32_t* b) {
    asm volatile("mma.sync.aligned.m16n8k16.row.col.f32.f16.f16.f32 "
        "{%0,%1,%2,%3}, {%4,%5,%6,%7}, {%8,%9}, {%0,%1,%2,%3};"
        : "+f"(c[0]), "+f"(c[1]), "+f"(c[2]), "+f"(c[3])
        : "r"(a[0]), "r"(a[1]), "r"(a[2]), "r"(a[3]), "r"(b[0]), "r"(b[1]));
}
__device__ __forceinline__ uint32_t f16x2_pack(__half a, __half b) {
    __half2 h = __halves2half2(a, b);
    return *reinterpret_cast<uint32_t*>(&h);
}
__device__ __forceinline__ uint32_t f16x2_hi(float f0, float f1, uint32_t& lo_out) {
    __half h0 = __float2half_rn(f0);
    __half h1 = __float2half_rn(f1);
    __half l0 = __float2half_rn(f0 - __half2float(h0));
    __half l1 = __float2half_rn(f1 - __half2float(h1));
    lo_out = f16x2_pack(l0, l1);
    return f16x2_pack(h0, h1);
}

// ---------------------------------------------------------------------------
// convert: P -> per-doc 32KB fp16-hi B-frag; Q -> per-group 32KB fp16 hi/lo A-frag.
// B: uint2 {hi_ri0, hi_ri1} at c*BTILE + ((k*16+n)*32+lane)*8
//    (h = k*16 + ri*8 + tg*2 {,+1}, d = n*8 + gr)
// A: per batch 16KB { hi 8KB | lo 8KB }; word at ((m*8+k)*32+lane)*16 + ri*4
//    (s = m*16 + gr + (ri&1)*8, h = k*16 + tg*2 + (ri>>1)*8 {,+1})
// group g holds batches {2g, 2g+1}.
// ---------------------------------------------------------------------------
__global__ void convert_kernel(const float* __restrict__ P, const float* __restrict__ Q) {
    int idx = blockIdx.x * blockDim.x + threadIdx.x;
    if (idx < CD * 4096) {
        int lane = idx & 31;
        int n    = (idx >> 5) & 15;
        int k    = (idx >> 9) & 7;
        int c    = idx >> 12;
        int tg = lane & 3, gr = lane >> 2;
        int d = n * 8 + gr;
        const float* s = P + ((size_t)c * DD + d) * HD;
        int h0 = k * 16 + tg * 2;
        float2 f0 = *reinterpret_cast<const float2*>(s + h0);
        float2 f1 = *reinterpret_cast<const float2*>(s + h0 + 8);
        uint2 v;
        v.x = f16x2_pack(__float2half_rn(f0.x), __float2half_rn(f0.y));
        v.y = f16x2_pack(__float2half_rn(f1.x), __float2half_rn(f1.y));
        *reinterpret_cast<uint2*>(g_P_sw + (size_t)c * BTILE
            + (size_t)(((k * 16 + n) * 32 + lane) * 8)) = v;
    } else {
        int qi = idx - CD * 4096;
        if (qi >= NGRP * 4096) return;
        int ri    = qi & 3;
        int lane  = (qi >> 2) & 31;
        int k     = (qi >> 7) & 7;
        int m     = (qi >> 10) & 1;
        int batch = (qi >> 11) & 1;
        int g     = qi >> 12;
        int tg = lane & 3, gr = lane >> 2;
        int srow = m * 16 + gr + (ri & 1) * 8;
        int h    = k * 16 + tg * 2 + (ri >> 1) * 8;
        int b    = g * 2 + batch;

        const float* s = Q + ((size_t)b * SQ + srow) * HD + h;
        uint32_t lo, hi = f16x2_hi(s[0], s[1], lo);

        size_t off = (size_t)g * ATILE + (size_t)batch * 16384
                   + (size_t)(((m * 8 + k) * 32 + lane) * 16 + ri * 4);
        *reinterpret_cast<uint32_t*>(g_Q_sw + off)        = hi;
        *reinterpret_cast<uint32_t*>(g_Q_sw + off + 8192) = lo;
    }
}

// ---------------------------------------------------------------------------
// maxsim: 296 persistent CTAs (2/SM), 256 threads. Tile t -> (g=t>>9, c=t&511).
// Warp w: batch = w>>2 (of the group's 2), d-quarter dq = w&3 (32 d each).
// 2-pass fp16 split: acc += Ah*Bh + Al*Bh. Last CTA computes the loss.
// ---------------------------------------------------------------------------
__global__ __launch_bounds__(256, 2)
void maxsim_kernel(float* __restrict__ out) {
    extern __shared__ __align__(128) unsigned char dyn[];
    __shared__ __align__(8) unsigned long long bars[5];  // QFULL, BFULL[2], BFREE[2]
    __shared__ __align__(16) float smax[2][2][32][4];    // [buf][batch][s][dq], 16B rows
    __shared__ float part[32];
    __shared__ unsigned int isLast;

    const int tid = threadIdx.x, w = tid >> 5, lane = tid & 31;
    const int batch = w >> 2, dq = w & 3;
    const int tg = lane & 3, gr = lane >> 2;

    const int start = (blockIdx.x * NTILE) / NCTA;
    const int end   = ((blockIdx.x + 1) * NTILE) / NCTA;
    const int L     = end - start;

    const uint32_t QFULL  = smem_u32(&bars[0]);
    const uint32_t BFULL0 = smem_u32(&bars[1]);
    const uint32_t BFREE0 = smem_u32(&bars[3]);
    const uint32_t A_S    = smem_u32(dyn);
    const uint32_t B_S    = smem_u32(dyn + ATILE);

    if (tid == 0) {
        mbar_init(QFULL, 1);
        mbar_init(BFULL0, 1);     mbar_init(BFULL0 + 8, 1);
        mbar_init(BFREE0, 8);     mbar_init(BFREE0 + 8, 8);
    }
    __syncthreads();

    // prefetch B for j = 0, 1
    if (tid == 0) {
        mbar_expect_tx(BFULL0, BTILE);
        bulk_copy_g2s(B_S, g_P_sw + (size_t)(start & 511) * BTILE, BTILE, BFULL0);
        if (L > 1) {
            mbar_expect_tx(BFULL0 + 8, BTILE);
            bulk_copy_g2s(B_S + BTILE, g_P_sw + (size_t)((start + 1) & 511) * BTILE, BTILE, BFULL0 + 8);
        }
    }

    int cur_g = -1, aloads = 0;

    for (int j = 0; j < L; ++j) {
        const int t = start + j;
        const int g = t >> 9;
        const int c = t & 511;
        const int st = j & 1;
        const int ph = (j >> 1) & 1;

        if (g != cur_g) {
            __syncthreads();  // all warps done with old A
            if (tid == 0) {
                mbar_expect_tx(QFULL, ATILE);
                bulk_copy_g2s(A_S, g_Q_sw + (size_t)g * ATILE, ATILE, QFULL);
            }
            mbar_wait(QFULL, aloads & 1);
            ++aloads;
            cur_g = g;
        }

        mbar_wait(BFULL0 + 8 * st, ph);

        const unsigned char* aBase = dyn + batch * 16384;          // hi; lo at +8192
        const unsigned char* stg   = dyn + ATILE + st * BTILE;     // fp16-hi B-frag

        float acc[2][4][4];
#pragma unroll
        for (int mm = 0; mm < 2; ++mm)
#pragma unroll
            for (int nn = 0; nn < 4; ++nn)
#pragma unroll
                for (int q = 0; q < 4; ++q) acc[mm][nn][q] = 0.0f;

#pragma unroll
        for (int k = 0; k < 8; ++k) {
            uint4 Ah0 = *reinterpret_cast<const uint4*>(aBase + ((0 * 8 + k) * 32 + lane) * 16);
            uint4 Ah1 = *reinterpret_cast<const uint4*>(aBase + ((1 * 8 + k) * 32 + lane) * 16);
            uint4 Al0 = *reinterpret_cast<const uint4*>(aBase + 8192 + ((0 * 8 + k) * 32 + lane) * 16);
            uint4 Al1 = *reinterpret_cast<const uint4*>(aBase + 8192 + ((1 * 8 + k) * 32 + lane) * 16);
#pragma unroll
            for (int n = 0; n < 4; ++n) {
                uint2 B = *reinterpret_cast<const uint2*>(
                    stg + ((k * 16 + dq * 4 + n) * 32 + lane) * 8);
                mma_f16(acc[0][n], &Ah0.x, &B.x);   // Ah*Bh
                mma_f16(acc[1][n], &Ah1.x, &B.x);
                mma_f16(acc[0][n], &Al0.x, &B.x);   // Al*Bh
                mma_f16(acc[1][n], &Al1.x, &B.x);
            }
        }

        if (lane == 0) mbar_arrive(BFREE0 + 8 * st);  // this stage consumed

        // producer: refill this stage with doc of tile j+2
        if (tid == 0 && j + 2 < L) {
            mbar_wait(BFREE0 + 8 * st, ph);
            mbar_expect_tx(BFULL0 + 8 * st, BTILE);
            bulk_copy_g2s(B_S + st * BTILE,
                          g_P_sw + (size_t)((start + j + 2) & 511) * BTILE, BTILE,
                          BFULL0 + 8 * st);
        }

        // ---- epilogue: max over this warp's 32 d, then cross-warp max + sum ----
        float m00 = -3.402823e38f, m01 = m00, m10 = m00, m11 = m00;
#pragma unroll
        for (int n = 0; n < 4; ++n) {
            m00 = fmaxf(m00, fmaxf(acc[0][n][0], acc[0][n][1]));
            m01 = fmaxf(m01, fmaxf(acc[0][n][2], acc[0][n][3]));
            m10 = fmaxf(m10, fmaxf(acc[1][n][0], acc[1][n][1]));
            m11 = fmaxf(m11, fmaxf(acc[1][n][2], acc[1][n][3]));
        }
#pragma unroll
        for (int off = 1; off <= 2; off <<= 1) {
            m00 = fmaxf(m00, __shfl_xor_sync(0xffffffffu, m00, off));
            m01 = fmaxf(m01, __shfl_xor_sync(0xffffffffu, m01, off));
            m10 = fmaxf(m10, __shfl_xor_sync(0xffffffffu, m10, off));
            m11 = fmaxf(m11, __shfl_xor_sync(0xffffffffu, m11, off));
        }
        const int buf = j & 1;
        if (tg == 0) {
            smax[buf][batch][gr][dq]      = m00;  // s = gr
            smax[buf][batch][gr + 8][dq]  = m01;  // s = gr+8
            smax[buf][batch][gr + 16][dq] = m10;  // s = 16+gr
            smax[buf][batch][gr + 24][dq] = m11;  // s = 24+gr
        }
        asm volatile("bar.sync %0, %1;" :: "r"(1 + batch), "r"(128) : "memory");
        if (dq == 0) {
            float4 q4 = *reinterpret_cast<const float4*>(&smax[buf][batch][lane][0]);
            float v = fmaxf(fmaxf(q4.x, q4.y), fmaxf(q4.z, q4.w));
#pragma unroll
            for (int off = 16; off; off >>= 1) v += __shfl_xor_sync(0xffffffffu, v, off);
            if (lane == 0) g_scores[(g * 2 + batch) * CD + c] = v * INV_TEMP;
        }
    }

    // ---- last CTA computes loss ----
    __syncthreads();
    if (tid == 0) {
        __threadfence();
        unsigned int o = atomicAdd(&g_done, 1u);
        isLast = (o == NCTA - 1) ? 1u : 0u;
    }
    __syncthreads();
    if (isLast) {
        __threadfence();
#pragma unroll
        for (int r = 0; r < 4; ++r) {
            int row = w * 4 + r;
            const float* rp = g_scores + row * CD;
            float4 v4[4];
#pragma unroll
            for (int k = 0; k < 4; ++k)
                v4[k] = *reinterpret_cast<const float4*>(rp + (lane + k * 32) * 4);
            float mx = -3.402823e38f;
#pragma unroll
            for (int k = 0; k < 4; ++k)
                mx = fmaxf(mx, fmaxf(fmaxf(v4[k].x, v4[k].y), fmaxf(v4[k].z, v4[k].w)));
#pragma unroll
            for (int off = 16; off; off >>= 1) mx = fmaxf(mx, __shfl_xor_sync(0xffffffffu, mx, off));
            float se = 0.0f;
#pragma unroll
            for (int k = 0; k < 4; ++k)
                se += expf(v4[k].x - mx) + expf(v4[k].y - mx) + expf(v4[k].z - mx) + expf(v4[k].w - mx);
#pragma unroll
            for (int off = 16; off; off >>= 1) se += __shfl_xor_sync(0xffffffffu, se, off);
            if (lane == 0) part[row] = mx + logf(se) - rp[0];
        }
        __syncthreads();
        if (w == 0) {
            float v = part[lane];
#pragma unroll
            for (int off = 16; off; off >>= 1) v += __shfl_xor_sync(0xffffffffu, v, off);
            if (lane == 0) out[0] = v * (1.0f / (float)BQ);
        }
        if (tid == 0) g_done = 0;   // reset for next graph replay
    }
}

extern "C" void kernel_launch(void* const* d_in, const int* in_sizes, int n_in,
                              void* d_out, int out_size) {
    const float* Q = (const float*)d_in[0];
    const float* P = (const float*)d_in[1];
    if (n_in >= 2 && in_sizes[0] != BQ * SQ * HD) {
        const float* t = Q; Q = P; P = t;
    }
    float* out = (float*)d_out;

    static bool attr_set = false;
    if (!attr_set) {
        cudaFuncSetAttribute(maxsim_kernel, cudaFuncAttributeMaxDynamicSharedMemorySize, SMEM_BYTES);
        attr_set = true;
    }

    const int conv_total = CD * 4096 + NGRP * 4096;
    convert_kernel<<<(conv_total + 255) / 256, 256>>>(P, Q);
    maxsim_kernel<<<NCTA, 256, SMEM_BYTES>>>(out);
}

// round 15
// speedup vs baseline: 3.5990x; 1.3859x over previous
#include <cuda_runtime.h>
#include <cuda_fp16.h>
#include <stdint.h>
#include <math.h>

#define BQ 32
#define SQ 32
#define HD 128
#define CD 512
#define DD 128
#define NGRP 16            // 16 groups of 2 batches (M=64 rows of A)
#define NTILE (NGRP * CD)  // 8192 (group, doc) tiles
#define NCTA 296           // 2 CTAs per SM
#define INV_TEMP 50.0f

#define ATILE 16384        // A tile per group: 2 batches x 8KB (fp16 hi only)
#define BTILE 32768        // B tile per doc: fp16 hi only
#define SMEM_BYTES (ATILE + 2 * BTILE)   // 80KB -> 2 CTAs/SM

__device__ float g_scores[BQ * CD];
__device__ unsigned int g_done = 0;
__device__ __align__(1024) unsigned char g_P_sw[(size_t)CD * BTILE];   // 16 MB, fp16-hi B-frag
__device__ __align__(1024) unsigned char g_Q_sw[(size_t)NGRP * ATILE]; // 256 KB, fp16-hi A-frag

// ---------------------------------------------------------------- PTX helpers
__device__ __forceinline__ uint32_t smem_u32(const void* p) {
    uint32_t a;
    asm("{ .reg .u64 t; cvta.to.shared.u64 t, %1; cvt.u32.u64 %0, t; }" : "=r"(a) : "l"(p));
    return a;
}
__device__ __forceinline__ void mbar_init(uint32_t m, uint32_t cnt) {
    asm volatile("mbarrier.init.shared.b64 [%0], %1;" :: "r"(m), "r"(cnt) : "memory");
}
__device__ __forceinline__ void mbar_expect_tx(uint32_t m, uint32_t bytes) {
    asm volatile("mbarrier.arrive.expect_tx.shared.b64 _, [%0], %1;" :: "r"(m), "r"(bytes) : "memory");
}
__device__ __forceinline__ void mbar_arrive(uint32_t m) {
    asm volatile("mbarrier.arrive.shared.b64 _, [%0];" :: "r"(m) : "memory");
}
__device__ __forceinline__ void mbar_wait(uint32_t m, uint32_t parity) {
    uint32_t done;
    asm volatile("{\n\t.reg .pred p;\n\t"
        "mbarrier.try_wait.parity.acquire.cta.shared::cta.b64 p, [%1], %2;\n\t"
        "selp.b32 %0, 1, 0, p;\n\t}"
        : "=r"(done) : "r"(m), "r"(parity) : "memory");
    while (!done) {
        asm volatile("{\n\t.reg .pred p;\n\t"
            "mbarrier.try_wait.parity.acquire.cta.shared::cta.b64 p, [%1], %2, 0x989680;\n\t"
            "selp.b32 %0, 1, 0, p;\n\t}"
            : "=r"(done) : "r"(m), "r"(parity) : "memory");
    }
}
__device__ __forceinline__ void bulk_copy_g2s(uint32_t dst, const void* src, uint32_t bytes, uint32_t mbar) {
    asm volatile("cp.async.bulk.shared::cluster.global.mbarrier::complete_tx::bytes [%0], [%1], %2, [%3];"
        :: "r"(dst), "l"(src), "r"(bytes), "r"(mbar) : "memory");
}
// warp mma: D(f32 16x8) += A(f16 16x16, row) * B(f16 16x8, col)
__device__ __forceinline__ void mma_f16(float* c, const uint32_t* a, const uint32_t* b) {
    asm volatile("mma.sync.aligned.m16n8k16.row.col.f32.f16.f16.f32 "
        "{%0,%1,%2,%3}, {%4,%5,%6,%7}, {%8,%9}, {%0,%1,%2,%3};"
        : "+f"(c[0]), "+f"(c[1]), "+f"(c[2]), "+f"(c[3])
        : "r"(a[0]), "r"(a[1]), "r"(a[2]), "r"(a[3]), "r"(b[0]), "r"(b[1]));
}
__device__ __forceinline__ uint32_t f16x2_pack(__half a, __half b) {
    __half2 h = __halves2half2(a, b);
    return *reinterpret_cast<uint32_t*>(&h);
}

// ---------------------------------------------------------------------------
// convert: P -> per-doc 32KB fp16-hi B-frag; Q -> per-group 16KB fp16-hi A-frag.
// B: uint2 {hi_ri0, hi_ri1} at c*BTILE + ((k*16+n)*32+lane)*8
//    (h = k*16 + ri*8 + tg*2 {,+1}, d = n*8 + gr)
// A: per batch 8KB; uint4 {ri0..ri3} at g*ATILE + batch*8192 + ((m*8+k)*32+lane)*16
//    (s = m*16 + gr + (ri&1)*8, h = k*16 + tg*2 + (ri>>1)*8 {,+1})
// group g holds batches {2g, 2g+1}.
// ---------------------------------------------------------------------------
__global__ void convert_kernel(const float* __restrict__ P, const float* __restrict__ Q) {
    int idx = blockIdx.x * blockDim.x + threadIdx.x;
    if (idx < CD * 4096) {
        int lane = idx & 31;
        int n    = (idx >> 5) & 15;
        int k    = (idx >> 9) & 7;
        int c    = idx >> 12;
        int tg = lane & 3, gr = lane >> 2;
        int d = n * 8 + gr;
        const float* s = P + ((size_t)c * DD + d) * HD;
        int h0 = k * 16 + tg * 2;
        float2 f0 = *reinterpret_cast<const float2*>(s + h0);
        float2 f1 = *reinterpret_cast<const float2*>(s + h0 + 8);
        uint2 v;
        v.x = f16x2_pack(__float2half_rn(f0.x), __float2half_rn(f0.y));
        v.y = f16x2_pack(__float2half_rn(f1.x), __float2half_rn(f1.y));
        *reinterpret_cast<uint2*>(g_P_sw + (size_t)c * BTILE
            + (size_t)(((k * 16 + n) * 32 + lane) * 8)) = v;
    } else {
        int qi = idx - CD * 4096;
        if (qi >= NGRP * 1024) return;   // one uint4 (4 ri words) per unit
        int lane  = qi & 31;
        int k     = (qi >> 5) & 7;
        int m     = (qi >> 8) & 1;
        int batch = (qi >> 9) & 1;
        int g     = qi >> 10;
        int tg = lane & 3, gr = lane >> 2;
        int b = g * 2 + batch;
        uint32_t wv[4];
#pragma unroll
        for (int ri = 0; ri < 4; ++ri) {
            int srow = m * 16 + gr + (ri & 1) * 8;
            int h    = k * 16 + tg * 2 + (ri >> 1) * 8;
            const float* s = Q + ((size_t)b * SQ + srow) * HD + h;
            wv[ri] = f16x2_pack(__float2half_rn(s[0]), __float2half_rn(s[1]));
        }
        uint4 v = {wv[0], wv[1], wv[2], wv[3]};
        *reinterpret_cast<uint4*>(g_Q_sw + (size_t)g * ATILE + (size_t)batch * 8192
            + (size_t)(((m * 8 + k) * 32 + lane) * 16)) = v;
    }
}

// ---------------------------------------------------------------------------
// maxsim: 296 persistent CTAs (2/SM), 256 threads. Tile t -> (g=t>>9, c=t&511).
// Warp w: batch = w>>2 (of the group's 2), d-quarter dq = w&3 (32 d each).
// Single-pass fp16-hi MMA. Last CTA computes the loss.
// ---------------------------------------------------------------------------
__global__ __launch_bounds__(256, 2)
void maxsim_kernel(float* __restrict__ out) {
    extern __shared__ __align__(128) unsigned char dyn[];
    __shared__ __align__(8) unsigned long long bars[5];  // QFULL, BFULL[2], BFREE[2]
    __shared__ __align__(16) float smax[2][2][32][4];    // [buf][batch][s][dq]
    __shared__ float part[32];
    __shared__ unsigned int isLast;

    const int tid = threadIdx.x, w = tid >> 5, lane = tid & 31;
    const int batch = w >> 2, dq = w & 3;
    const int tg = lane & 3, gr = lane >> 2;

    const int start = (blockIdx.x * NTILE) / NCTA;
    const int end   = ((blockIdx.x + 1) * NTILE) / NCTA;
    const int L     = end - start;

    const uint32_t QFULL  = smem_u32(&bars[0]);
    const uint32_t BFULL0 = smem_u32(&bars[1]);
    const uint32_t BFREE0 = smem_u32(&bars[3]);
    const uint32_t A_S    = smem_u32(dyn);
    const uint32_t B_S    = smem_u32(dyn + ATILE);

    if (tid == 0) {
        mbar_init(QFULL, 1);
        mbar_init(BFULL0, 1);     mbar_init(BFULL0 + 8, 1);
        mbar_init(BFREE0, 8);     mbar_init(BFREE0 + 8, 8);
    }
    __syncthreads();

    // prefetch B for j = 0, 1
    if (tid == 0) {
        mbar_expect_tx(BFULL0, BTILE);
        bulk_copy_g2s(B_S, g_P_sw + (size_t)(start & 511) * BTILE, BTILE, BFULL0);
        if (L > 1) {
            mbar_expect_tx(BFULL0 + 8, BTILE);
            bulk_copy_g2s(B_S + BTILE, g_P_sw + (size_t)((start + 1) & 511) * BTILE, BTILE, BFULL0 + 8);
        }
    }

    int cur_g = -1, aloads = 0;

    for (int j = 0; j < L; ++j) {
        const int t = start + j;
        const int g = t >> 9;
        const int c = t & 511;
        const int st = j & 1;
        const int ph = (j >> 1) & 1;

        if (g != cur_g) {
            __syncthreads();  // all warps done with old A
            if (tid == 0) {
                mbar_expect_tx(QFULL, ATILE);
                bulk_copy_g2s(A_S, g_Q_sw + (size_t)g * ATILE, ATILE, QFULL);
            }
            mbar_wait(QFULL, aloads & 1);
            ++aloads;
            cur_g = g;
        }

        mbar_wait(BFULL0 + 8 * st, ph);

        const unsigned char* aBase = dyn + batch * 8192;           // fp16-hi A-frag
        const unsigned char* stg   = dyn + ATILE + st * BTILE;     // fp16-hi B-frag

        float acc[2][4][4];
#pragma unroll
        for (int mm = 0; mm < 2; ++mm)
#pragma unroll
            for (int nn = 0; nn < 4; ++nn)
#pragma unroll
                for (int q = 0; q < 4; ++q) acc[mm][nn][q] = 0.0f;

#pragma unroll
        for (int k = 0; k < 8; ++k) {
            uint4 Ah0 = *reinterpret_cast<const uint4*>(aBase + ((0 * 8 + k) * 32 + lane) * 16);
            uint4 Ah1 = *reinterpret_cast<const uint4*>(aBase + ((1 * 8 + k) * 32 + lane) * 16);
#pragma unroll
            for (int n = 0; n < 4; ++n) {
                uint2 B = *reinterpret_cast<const uint2*>(
                    stg + ((k * 16 + dq * 4 + n) * 32 + lane) * 8);
                mma_f16(acc[0][n], &Ah0.x, &B.x);
                mma_f16(acc[1][n], &Ah1.x, &B.x);
            }
        }

        if (lane == 0) mbar_arrive(BFREE0 + 8 * st);  // this stage consumed

        // producer: refill this stage with doc of tile j+2
        if (tid == 0 && j + 2 < L) {
            mbar_wait(BFREE0 + 8 * st, ph);
            mbar_expect_tx(BFULL0 + 8 * st, BTILE);
            bulk_copy_g2s(B_S + st * BTILE,
                          g_P_sw + (size_t)((start + j + 2) & 511) * BTILE, BTILE,
                          BFULL0 + 8 * st);
        }

        // ---- epilogue: max over this warp's 32 d, then cross-warp max + sum ----
        float m00 = -3.402823e38f, m01 = m00, m10 = m00, m11 = m00;
#pragma unroll
        for (int n = 0; n < 4; ++n) {
            m00 = fmaxf(m00, fmaxf(acc[0][n][0], acc[0][n][1]));
            m01 = fmaxf(m01, fmaxf(acc[0][n][2], acc[0][n][3]));
            m10 = fmaxf(m10, fmaxf(acc[1][n][0], acc[1][n][1]));
            m11 = fmaxf(m11, fmaxf(acc[1][n][2], acc[1][n][3]));
        }
#pragma unroll
        for (int off = 1; off <= 2; off <<= 1) {
            m00 = fmaxf(m00, __shfl_xor_sync(0xffffffffu, m00, off));
            m01 = fmaxf(m01, __shfl_xor_sync(0xffffffffu, m01, off));
            m10 = fmaxf(m10, __shfl_xor_sync(0xffffffffu, m10, off));
            m11 = fmaxf(m11, __shfl_xor_sync(0xffffffffu, m11, off));
        }
        const int buf = j & 1;
        if (tg == 0) {
            smax[buf][batch][gr][dq]      = m00;  // s = gr
            smax[buf][batch][gr + 8][dq]  = m01;  // s = gr+8
            smax[buf][batch][gr + 16][dq] = m10;  // s = 16+gr
            smax[buf][batch][gr + 24][dq] = m11;  // s = 24+gr
        }
        asm volatile("bar.sync %0, %1;" :: "r"(1 + batch), "r"(128) : "memory");
        if (dq == 0) {
            float4 q4 = *reinterpret_cast<const float4*>(&smax[buf][batch][lane][0]);
            float v = fmaxf(fmaxf(q4.x, q4.y), fmaxf(q4.z, q4.w));
#pragma unroll
            for (int off = 16; off; off >>= 1) v += __shfl_xor_sync(0xffffffffu, v, off);
            if (lane == 0) g_scores[(g * 2 + batch) * CD + c] = v * INV_TEMP;
        }
    }

    // ---- last CTA computes loss ----
    __syncthreads();
    if (tid == 0) {
        __threadfence();
        unsigned int o = atomicAdd(&g_done, 1u);
        isLast = (o == NCTA - 1) ? 1u : 0u;
    }
    __syncthreads();
    if (isLast) {
        __threadfence();
#pragma unroll
        for (int r = 0; r < 4; ++r) {
            int row = w * 4 + r;
            const float* rp = g_scores + row * CD;
            float4 v4[4];
#pragma unroll
            for (int k = 0; k < 4; ++k)
                v4[k] = *reinterpret_cast<const float4*>(rp + (lane + k * 32) * 4);
            float mx = -3.402823e38f;
#pragma unroll
            for (int k = 0; k < 4; ++k)
                mx = fmaxf(mx, fmaxf(fmaxf(v4[k].x, v4[k].y), fmaxf(v4[k].z, v4[k].w)));
#pragma unroll
            for (int off = 16; off; off >>= 1) mx = fmaxf(mx, __shfl_xor_sync(0xffffffffu, mx, off));
            float se = 0.0f;
#pragma unroll
            for (int k = 0; k < 4; ++k)
                se += expf(v4[k].x - mx) + expf(v4[k].y - mx) + expf(v4[k].z - mx) + expf(v4[k].w - mx);
#pragma unroll
            for (int off = 16; off; off >>= 1) se += __shfl_xor_sync(0xffffffffu, se, off);
            if (lane == 0) part[row] = mx + logf(se) - rp[0];
        }
        __syncthreads();
        if (w == 0) {
            float v = part[lane];
#pragma unroll
            for (int off = 16; off; off >>= 1) v += __shfl_xor_sync(0xffffffffu, v, off);
            if (lane == 0) out[0] = v * (1.0f / (float)BQ);
        }
        if (tid == 0) g_done = 0;   // reset for next graph replay
    }
}

extern "C" void kernel_launch(void* const* d_in, const int* in_sizes, int n_in,
                              void* d_out, int out_size) {
    const float* Q = (const float*)d_in[0];
    const float* P = (const float*)d_in[1];
    if (n_in >= 2 && in_sizes[0] != BQ * SQ * HD) {
        const float* t = Q; Q = P; P = t;
    }
    float* out = (float*)d_out;

    static bool attr_set = false;
    if (!attr_set) {
        cudaFuncSetAttribute(maxsim_kernel, cudaFuncAttributeMaxDynamicSharedMemorySize, SMEM_BYTES);
        attr_set = true;
    }

    const int conv_total = CD * 4096 + NGRP * 1024;
    convert_kernel<<<(conv_total + 255) / 256, 256>>>(P, Q);
    maxsim_kernel<<<NCTA, 256, SMEM_BYTES>>>(out);
}

// round 17
// speedup vs baseline: 4.0361x; 1.1214x over previous
#include <cuda_runtime.h>
#include <cuda_fp16.h>
#include <stdint.h>
#include <math.h>

#define BQ 32
#define SQ 32
#define HD 128
#define CD 512
#define DD 128
#define NGRP 16            // 16 groups of 2 batches (M=64 rows of A)
#define NTILE (NGRP * CD)  // 8192 (group, doc) tiles
#define NCTA 296           // 2 CTAs per SM
#define INV_TEMP 50.0f

#define ATILE 16384        // A block per group in GLOBAL: 2 batches x 8KB (fp16 hi)
#define BTILE 32768        // B tile per doc: fp16 hi only
#define SMEM_BYTES (2 * BTILE)   // 64KB: 2 B stages only (A lives in registers)

__device__ float g_scores[BQ * CD];
__device__ unsigned int g_done = 0;
__device__ __align__(1024) unsigned char g_P_sw[(size_t)CD * BTILE];   // 16 MB, fp16-hi B-frag
__device__ __align__(1024) unsigned char g_Q_sw[(size_t)NGRP * ATILE]; // 256 KB, fp16-hi A-frag

// ---------------------------------------------------------------- PTX helpers
__device__ __forceinline__ uint32_t smem_u32(const void* p) {
    uint32_t a;
    asm("{ .reg .u64 t; cvta.to.shared.u64 t, %1; cvt.u32.u64 %0, t; }" : "=r"(a) : "l"(p));
    return a;
}
__device__ __forceinline__ void mbar_init(uint32_t m, uint32_t cnt) {
    asm volatile("mbarrier.init.shared.b64 [%0], %1;" :: "r"(m), "r"(cnt) : "memory");
}
__device__ __forceinline__ void mbar_expect_tx(uint32_t m, uint32_t bytes) {
    asm volatile("mbarrier.arrive.expect_tx.shared.b64 _, [%0], %1;" :: "r"(m), "r"(bytes) : "memory");
}
__device__ __forceinline__ void mbar_arrive(uint32_t m) {
    asm volatile("mbarrier.arrive.shared.b64 _, [%0];" :: "r"(m) : "memory");
}
__device__ __forceinline__ void mbar_wait(uint32_t m, uint32_t parity) {
    uint32_t done;
    asm volatile("{\n\t.reg .pred p;\n\t"
        "mbarrier.try_wait.parity.acquire.cta.shared::cta.b64 p, [%1], %2;\n\t"
        "selp.b32 %0, 1, 0, p;\n\t}"
        : "=r"(done) : "r"(m), "r"(parity) : "memory");
    while (!done) {
        asm volatile("{\n\t.reg .pred p;\n\t"
            "mbarrier.try_wait.parity.acquire.cta.shared::cta.b64 p, [%1], %2, 0x989680;\n\t"
            "selp.b32 %0, 1, 0, p;\n\t}"
            : "=r"(done) : "r"(m), "r"(parity) : "memory");
    }
}
__device__ __forceinline__ void bulk_copy_g2s(uint32_t dst, const void* src, uint32_t bytes, uint32_t mbar) {
    asm volatile("cp.async.bulk.shared::cluster.global.mbarrier::complete_tx::bytes [%0], [%1], %2, [%3];"
        :: "r"(dst), "l"(src), "r"(bytes), "r"(mbar) : "memory");
}
// warp mma: D(f32 16x8) += A(f16 16x16, row) * B(f16 16x8, col)
__device__ __forceinline__ void mma_f16(float* c, const uint32_t* a, const uint32_t* b) {
    asm volatile("mma.sync.aligned.m16n8k16.row.col.f32.f16.f16.f32 "
        "{%0,%1,%2,%3}, {%4,%5,%6,%7}, {%8,%9}, {%0,%1,%2,%3};"
        : "+f"(c[0]), "+f"(c[1]), "+f"(c[2]), "+f"(c[3])
        : "r"(a[0]), "r"(a[1]), "r"(a[2]), "r"(a[3]), "r"(b[0]), "r"(b[1]));
}
__device__ __forceinline__ uint32_t f16x2_pack(__half a, __half b) {
    __half2 h = __halves2half2(a, b);
    return *reinterpret_cast<uint32_t*>(&h);
}

// ---------------------------------------------------------------------------
// convert: P -> per-doc 32KB fp16-hi B-frag; Q -> per-group 16KB fp16-hi A-frag.
// B: uint2 {hi_ri0, hi_ri1} at c*BTILE + ((k*16+n)*32+lane)*8
//    (h = k*16 + ri*8 + tg*2 {,+1}, d = n*8 + gr)
// A: per batch 8KB; uint4 {ri0..ri3} at g*ATILE + batch*8192 + ((m*8+k)*32+lane)*16
//    (s = m*16 + gr + (ri&1)*8, h = k*16 + tg*2 + (ri>>1)*8 {,+1})
// group g holds batches {2g, 2g+1}.
// ---------------------------------------------------------------------------
__global__ void convert_kernel(const float* __restrict__ P, const float* __restrict__ Q) {
    int idx = blockIdx.x * blockDim.x + threadIdx.x;
    if (idx < CD * 4096) {
        int lane = idx & 31;
        int n    = (idx >> 5) & 15;
        int k    = (idx >> 9) & 7;
        int c    = idx >> 12;
        int tg = lane & 3, gr = lane >> 2;
        int d = n * 8 + gr;
        const float* s = P + ((size_t)c * DD + d) * HD;
        int h0 = k * 16 + tg * 2;
        float2 f0 = *reinterpret_cast<const float2*>(s + h0);
        float2 f1 = *reinterpret_cast<const float2*>(s + h0 + 8);
        uint2 v;
        v.x = f16x2_pack(__float2half_rn(f0.x), __float2half_rn(f0.y));
        v.y = f16x2_pack(__float2half_rn(f1.x), __float2half_rn(f1.y));
        *reinterpret_cast<uint2*>(g_P_sw + (size_t)c * BTILE
            + (size_t)(((k * 16 + n) * 32 + lane) * 8)) = v;
    } else {
        int qi = idx - CD * 4096;
        if (qi >= NGRP * 1024) return;   // one uint4 (4 ri words) per unit
        int lane  = qi & 31;
        int k     = (qi >> 5) & 7;
        int m     = (qi >> 8) & 1;
        int batch = (qi >> 9) & 1;
        int g     = qi >> 10;
        int tg = lane & 3, gr = lane >> 2;
        int b = g * 2 + batch;
        uint32_t wv[4];
#pragma unroll
        for (int ri = 0; ri < 4; ++ri) {
            int srow = m * 16 + gr + (ri & 1) * 8;
            int h    = k * 16 + tg * 2 + (ri >> 1) * 8;
            const float* s = Q + ((size_t)b * SQ + srow) * HD + h;
            wv[ri] = f16x2_pack(__float2half_rn(s[0]), __float2half_rn(s[1]));
        }
        uint4 v = {wv[0], wv[1], wv[2], wv[3]};
        *reinterpret_cast<uint4*>(g_Q_sw + (size_t)g * ATILE + (size_t)batch * 8192
            + (size_t)(((m * 8 + k) * 32 + lane) * 16)) = v;
    }
}

// ---------------------------------------------------------------------------
// maxsim: 296 persistent CTAs (2/SM), 256 threads. Tile t -> (g=t>>9, c=t&511).
// Warp w: batch = w>>2 (of the group's 2), d-quarter dq = w&3 (32 d each).
// A fragments held in REGISTERS across the doc loop (loaded from global on
// group switch). Only B streams through smem. Last CTA computes the loss.
// ---------------------------------------------------------------------------
__global__ __launch_bounds__(256, 2)
void maxsim_kernel(float* __restrict__ out) {
    extern __shared__ __align__(128) unsigned char dyn[];
    __shared__ __align__(8) unsigned long long bars[4];  // BFULL[2], BFREE[2]
    __shared__ __align__(16) float smax[2][2][32][4];    // [buf][batch][s][dq]
    __shared__ float part[32];
    __shared__ unsigned int isLast;

    const int tid = threadIdx.x, w = tid >> 5, lane = tid & 31;
    const int batch = w >> 2, dq = w & 3;
    const int tg = lane & 3, gr = lane >> 2;

    const int start = (blockIdx.x * NTILE) / NCTA;
    const int end   = ((blockIdx.x + 1) * NTILE) / NCTA;
    const int L     = end - start;

    const uint32_t BFULL0 = smem_u32(&bars[0]);
    const uint32_t BFREE0 = smem_u32(&bars[2]);
    const uint32_t B_S    = smem_u32(dyn);

    if (tid == 0) {
        mbar_init(BFULL0, 1);     mbar_init(BFULL0 + 8, 1);
        mbar_init(BFREE0, 8);     mbar_init(BFREE0 + 8, 8);
    }
    __syncthreads();

    // prefetch B for j = 0, 1
    if (tid == 0) {
        mbar_expect_tx(BFULL0, BTILE);
        bulk_copy_g2s(B_S, g_P_sw + (size_t)(start & 511) * BTILE, BTILE, BFULL0);
        if (L > 1) {
            mbar_expect_tx(BFULL0 + 8, BTILE);
            bulk_copy_g2s(B_S + BTILE, g_P_sw + (size_t)((start + 1) & 511) * BTILE, BTILE, BFULL0 + 8);
        }
    }

    uint4 A0[8], A1[8];   // this warp's A fragments (m=0,1), held across docs
    int cur_g = -1;

    for (int j = 0; j < L; ++j) {
        const int t = start + j;
        const int g = t >> 9;
        const int c = t & 511;
        const int st = j & 1;
        const int ph = (j >> 1) & 1;

        if (g != cur_g) {
            const uint4* aG = reinterpret_cast<const uint4*>(
                g_Q_sw + (size_t)g * ATILE + (size_t)batch * 8192);
#pragma unroll
            for (int k = 0; k < 8; ++k) {
                A0[k] = __ldg(aG + ((0 * 8 + k) * 32 + lane));
                A1[k] = __ldg(aG + ((1 * 8 + k) * 32 + lane));
            }
            cur_g = g;
        }

        mbar_wait(BFULL0 + 8 * st, ph);

        const unsigned char* stg = dyn + st * BTILE;   // fp16-hi B-frag

        float acc[2][4][4];
#pragma unroll
        for (int mm = 0; mm < 2; ++mm)
#pragma unroll
            for (int nn = 0; nn < 4; ++nn)
#pragma unroll
                for (int q = 0; q < 4; ++q) acc[mm][nn][q] = 0.0f;

#pragma unroll
        for (int k = 0; k < 8; ++k) {
#pragma unroll
            for (int n = 0; n < 4; ++n) {
                uint2 B = *reinterpret_cast<const uint2*>(
                    stg + ((k * 16 + dq * 4 + n) * 32 + lane) * 8);
                mma_f16(acc[0][n], &A0[k].x, &B.x);
                mma_f16(acc[1][n], &A1[k].x, &B.x);
            }
        }

        if (lane == 0) mbar_arrive(BFREE0 + 8 * st);  // this stage consumed

        // producer: refill this stage with doc of tile j+2
        if (tid == 0 && j + 2 < L) {
            mbar_wait(BFREE0 + 8 * st, ph);
            mbar_expect_tx(BFULL0 + 8 * st, BTILE);
            bulk_copy_g2s(B_S + st * BTILE,
                          g_P_sw + (size_t)((start + j + 2) & 511) * BTILE, BTILE,
                          BFULL0 + 8 * st);
        }

        // ---- epilogue: max over this warp's 32 d, then cross-warp max + sum ----
        float m00 = -3.402823e38f, m01 = m00, m10 = m00, m11 = m00;
#pragma unroll
        for (int n = 0; n < 4; ++n) {
            m00 = fmaxf(m00, fmaxf(acc[0][n][0], acc[0][n][1]));
            m01 = fmaxf(m01, fmaxf(acc[0][n][2], acc[0][n][3]));
            m10 = fmaxf(m10, fmaxf(acc[1][n][0], acc[1][n][1]));
            m11 = fmaxf(m11, fmaxf(acc[1][n][2], acc[1][n][3]));
        }
#pragma unroll
        for (int off = 1; off <= 2; off <<= 1) {
            m00 = fmaxf(m00, __shfl_xor_sync(0xffffffffu, m00, off));
            m01 = fmaxf(m01, __shfl_xor_sync(0xffffffffu, m01, off));
            m10 = fmaxf(m10, __shfl_xor_sync(0xffffffffu, m10, off));
            m11 = fmaxf(m11, __shfl_xor_sync(0xffffffffu, m11, off));
        }
        const int buf = j & 1;
        if (tg == 0) {
            smax[buf][batch][gr][dq]      = m00;  // s = gr
            smax[buf][batch][gr + 8][dq]  = m01;  // s = gr+8
            smax[buf][batch][gr + 16][dq] = m10;  // s = 16+gr
            smax[buf][batch][gr + 24][dq] = m11;  // s = 24+gr
        }
        asm volatile("bar.sync %0, %1;" :: "r"(1 + batch), "r"(128) : "memory");
        if (dq == 0) {
            float4 q4 = *reinterpret_cast<const float4*>(&smax[buf][batch][lane][0]);
            float v = fmaxf(fmaxf(q4.x, q4.y), fmaxf(q4.z, q4.w));
#pragma unroll
            for (int off = 16; off; off >>= 1) v += __shfl_xor_sync(0xffffffffu, v, off);
            if (lane == 0) g_scores[(g * 2 + batch) * CD + c] = v * INV_TEMP;
        }
    }

    // ---- last CTA computes loss ----
    __syncthreads();
    if (tid == 0) {
        __threadfence();
        unsigned int o = atomicAdd(&g_done, 1u);
        isLast = (o == NCTA - 1) ? 1u : 0u;
    }
    __syncthreads();
    if (isLast) {
        __threadfence();
#pragma unroll
        for (int r = 0; r < 4; ++r) {
            int row = w * 4 + r;
            const float* rp = g_scores + row * CD;
            float4 v4[4];
#pragma unroll
            for (int k = 0; k < 4; ++k)
                v4[k] = *reinterpret_cast<const float4*>(rp + (lane + k * 32) * 4);
            float mx = -3.402823e38f;
#pragma unroll
            for (int k = 0; k < 4; ++k)
                mx = fmaxf(mx, fmaxf(fmaxf(v4[k].x, v4[k].y), fmaxf(v4[k].z, v4[k].w)));
#pragma unroll
            for (int off = 16; off; off >>= 1) mx = fmaxf(mx, __shfl_xor_sync(0xffffffffu, mx, off));
            float se = 0.0f;
#pragma unroll
            for (int k = 0; k < 4; ++k)
                se += expf(v4[k].x - mx) + expf(v4[k].y - mx) + expf(v4[k].z - mx) + expf(v4[k].w - mx);
#pragma unroll
            for (int off = 16; off; off >>= 1) se += __shfl_xor_sync(0xffffffffu, se, off);
            if (lane == 0) part[row] = mx + logf(se) - rp[0];
        }
        __syncthreads();
        if (w == 0) {
            float v = part[lane];
#pragma unroll
            for (int off = 16; off; off >>= 1) v += __shfl_xor_sync(0xffffffffu, v, off);
            if (lane == 0) out[0] = v * (1.0f / (float)BQ);
        }
        if (tid == 0) g_done = 0;   // reset for next graph replay
    }
}

extern "C" void kernel_launch(void* const* d_in, const int* in_sizes, int n_in,
                              void* d_out, int out_size) {
    const float* Q = (const float*)d_in[0];
    const float* P = (const float*)d_in[1];
    if (n_in >= 2 && in_sizes[0] != BQ * SQ * HD) {
        const float* t = Q; Q = P; P = t;
    }
    float* out = (float*)d_out;

    static bool attr_set = false;
    if (!attr_set) {
        cudaFuncSetAttribute(maxsim_kernel, cudaFuncAttributeMaxDynamicSharedMemorySize, SMEM_BYTES);
        attr_set = true;
    }

    const int conv_total = CD * 4096 + NGRP * 1024;
    convert_kernel<<<(conv_total + 255) / 256, 256>>>(P, Q);
    maxsim_kernel<<<NCTA, 256, SMEM_BYTES>>>(out);
}